// round 4
// baseline (speedup 1.0000x reference)
#include <cuda_runtime.h>
#include <cuda_bf16.h>
#include <stdint.h>

#define BATCH 8
#define NN    1024
#define FF    128

// ---------------- scratch (no allocations allowed -> __device__ globals) --------
__device__ float    g_H[(size_t)BATCH * 12 * NN * FF];     // 48 MB
__device__ float    g_outacc[(size_t)BATCH * NN * FF];     // 4 MB (self contribution)
__device__ float    g_part[12][(size_t)BATCH * NN * FF];   // 48 MB per-op partials
__device__ float    g_esrc[BATCH * 12 * NN];
__device__ float    g_edst[BATCH * 12 * NN];
__device__ float    g_Htot[BATCH * 12 * FF];
__device__ uint32_t g_rowbits[(size_t)BATCH * 6 * NN * 32];  // rel 0-2, 6-8 row masks
__device__ uint32_t g_bitsT[(size_t)BATCH * 3 * NN * 32];    // rel 6-8 transposed masks
__device__ uint32_t g_dbits[BATCH * 3 * 32];                 // diag masks (rel 3-5)

// =========== fused bitpack: row masks, transposed masks, diag, Htot zero ========
__global__ __launch_bounds__(256) void bitpack_kernel(const float* __restrict__ adjs)
{
    const int slab = blockIdx.x, y = blockIdx.y, b = blockIdx.z;
    const int warp = threadIdx.x >> 5, lane = threadIdx.x & 31;

    if (y == 6) {
        if (slab < 3) {                       // diag masks for rel 3..5
            #pragma unroll
            for (int rr = 0; rr < 4; rr++) {
                const int i = rr * 256 + threadIdx.x;
                float v = adjs[(((size_t)(b * 9 + 3 + slab)) * NN + i) * NN + i];
                unsigned m = __ballot_sync(0xffffffffu, v > 0.f);
                if (lane == 0) g_dbits[(b * 3 + slab) * 32 + (i >> 5)] = m;
            }
        } else if (slab == 3 && b == 0) {     // zero Htot (before gemm's atomics)
            for (int t = threadIdx.x; t < BATCH * 12 * FF; t += 256) g_Htot[t] = 0.f;
        }
        return;
    }

    const bool doT = (y >= 3);
    const int rel = doT ? (y + 3) : y;        // y 0-2 -> rel 0-2 ; y 3-5 -> rel 6-8
    __shared__ uint32_t sw[32 * 32];

    #pragma unroll
    for (int rr = 0; rr < 4; rr++) {
        const int row = slab * 32 + warp * 4 + rr;
        const float* rp = adjs + (((size_t)(b * 9 + rel)) * NN + row) * NN;
        uint32_t myw = 0;
        #pragma unroll 4
        for (int it = 0; it < 32; it++) {
            float v = rp[it * 32 + lane];
            unsigned mm = __ballot_sync(0xffffffffu, v > 0.f);
            if (lane == it) myw = mm;
        }
        g_rowbits[(((size_t)(b * 6 + y)) * NN + row) * 32 + lane] = myw;
        if (doT) sw[(warp * 4 + rr) * 32 + lane] = myw;
    }
    if (doT) {
        __syncthreads();
        for (int c = threadIdx.x; c < NN; c += 256) {
            const int word = c >> 5, bit = c & 31;
            uint32_t t = 0;
            #pragma unroll
            for (int r = 0; r < 32; r++)
                t |= ((sw[r * 32 + word] >> bit) & 1u) << r;
            g_bitsT[(((size_t)(b * 3 + (y - 3))) * NN + c) * 32 + slab] = t;
        }
    }
}

// =============================== tf32 GEMM ======================================
// C[1024,128] = X @ W^T + bias ; 13 weight sets per batch. Fragment-swizzled smem.
// 512 threads, 4x4 warp grid, 32x32 warp tiles -> 16 warps/CTA for latency hiding.
__device__ __forceinline__ uint32_t f2tf32(float f)
{
    uint32_t r;
    asm("cvt.rna.tf32.f32 %0, %1;" : "=r"(r) : "f"(f));
    return r;
}

__device__ __forceinline__ void mma_tf32(float4& d, const uint4 a, const uint2 b)
{
    asm volatile(
        "mma.sync.aligned.m16n8k8.row.col.f32.tf32.tf32.f32 "
        "{%0,%1,%2,%3}, {%4,%5,%6,%7}, {%8,%9}, {%0,%1,%2,%3};"
        : "+f"(d.x), "+f"(d.y), "+f"(d.z), "+f"(d.w)
        : "r"(a.x), "r"(a.y), "r"(a.z), "r"(a.w), "r"(b.x), "r"(b.y));
}

#define GEMM_SMEM (32768 * 4)   // As 16384 + Ws 16384 uint32

__global__ __launch_bounds__(512) void gemm_kernel(
    const float* __restrict__ x,
    const float* __restrict__ fc_w,  const float* __restrict__ fc_b,
    const float* __restrict__ fwd_w, const float* __restrict__ fwd_b,
    const float* __restrict__ bwd_w, const float* __restrict__ bwd_b,
    const float* __restrict__ self_w, const float* __restrict__ self_b,
    const float* __restrict__ bias)
{
    extern __shared__ uint32_t sm[];
    uint32_t* As = sm;            // [mtile8][kstep16][lane32][reg4]
    uint32_t* Ws = sm + 16384;    // [ntile16][kstep16][lane32][reg2]

    const int rb = blockIdx.x, r = blockIdx.y, b = blockIdx.z;
    const int tid = threadIdx.x;

    const float* X = x + (size_t)b * NN * FF + (size_t)rb * 128 * FF;
    const float* Wp; const float* bv; const float* bv2 = nullptr; float* dst;
    if (r < 6)       { Wp = fc_w  + r * FF * FF;       bv = fc_b  + r * FF;
                       dst = g_H + ((size_t)(b * 12 + r)) * NN * FF; }
    else if (r < 9)  { Wp = fwd_w + (r - 6) * FF * FF; bv = fwd_b + (r - 6) * FF;
                       dst = g_H + ((size_t)(b * 12 + r)) * NN * FF; }
    else if (r < 12) { Wp = bwd_w + (r - 9) * FF * FF; bv = bwd_b + (r - 9) * FF;
                       dst = g_H + ((size_t)(b * 12 + r)) * NN * FF; }
    else             { Wp = self_w; bv = self_b; bv2 = bias;
                       dst = g_outacc + (size_t)b * NN * FF; }

    // ---- fill A fragments (X tile 128x128, tf32) ----
    for (int t = tid; t < 4096; t += 512) {
        const int row = t >> 5;
        const int c = (t & 31) << 2;
        float4 v = *(const float4*)(X + (size_t)row * FF + c);
        const int m = row >> 4, lr = row & 15;
        const int s = c >> 3;
        const int reg = (lr >> 3) + ((c & 4) ? 2 : 0);
        uint32_t* base = As + (((m << 4) + s) << 7) + (((lr & 7) << 2) << 2) + reg;
        base[0]  = f2tf32(v.x);
        base[4]  = f2tf32(v.y);
        base[8]  = f2tf32(v.z);
        base[12] = f2tf32(v.w);
    }
    // ---- fill B fragments (W 128x128, tf32) ----
    for (int t = tid; t < 4096; t += 512) {
        const int n = t >> 5;
        const int k = (t & 31) << 2;
        float4 v = *(const float4*)(Wp + (size_t)n * FF + k);
        const int nt = n >> 3;
        const int s = k >> 3;
        const int reg = (k & 4) ? 1 : 0;
        uint32_t* base = Ws + (((nt << 4) + s) << 6) + (((n & 7) << 2) << 1) + reg;
        base[0] = f2tf32(v.x);
        base[2] = f2tf32(v.y);
        base[4] = f2tf32(v.z);
        base[6] = f2tf32(v.w);
    }
    __syncthreads();

    const int warp = tid >> 5, lane = tid & 31;
    const int wm = warp >> 2, wn = warp & 3;   // 4x4 warp grid, 32x32 tiles

    float4 acc[2][4];
    #pragma unroll
    for (int i = 0; i < 2; i++)
        #pragma unroll
        for (int j = 0; j < 4; j++) acc[i][j] = make_float4(0.f, 0.f, 0.f, 0.f);

    #pragma unroll
    for (int s = 0; s < 16; s++) {
        uint4 a[2]; uint2 bb[4];
        #pragma unroll
        for (int i = 0; i < 2; i++)
            a[i] = *(const uint4*)(As + ((((wm * 2 + i) << 4) + s) << 7) + (lane << 2));
        #pragma unroll
        for (int j = 0; j < 4; j++)
            bb[j] = *(const uint2*)(Ws + ((((wn * 4 + j) << 4) + s) << 6) + (lane << 1));
        #pragma unroll
        for (int i = 0; i < 2; i++)
            #pragma unroll
            for (int j = 0; j < 4; j++)
                mma_tf32(acc[i][j], a[i], bb[j]);
    }

    const int g = lane >> 2, t4 = lane & 3;
    float b0[4], b1[4];
    #pragma unroll
    for (int j = 0; j < 4; j++) {
        const int col = (wn * 4 + j) * 8 + 2 * t4;
        b0[j] = bv[col];     b1[j] = bv[col + 1];
        if (bv2) { b0[j] += bv2[col]; b1[j] += bv2[col + 1]; }
    }
    #pragma unroll
    for (int i = 0; i < 2; i++) {
        const int row0 = rb * 128 + (wm * 2 + i) * 16 + g;
        #pragma unroll
        for (int j = 0; j < 4; j++) {
            const int col = (wn * 4 + j) * 8 + 2 * t4;
            float2 lo = make_float2(acc[i][j].x + b0[j], acc[i][j].y + b1[j]);
            float2 hi = make_float2(acc[i][j].z + b0[j], acc[i][j].w + b1[j]);
            *(float2*)(dst + (size_t)row0 * FF + col)       = lo;
            *(float2*)(dst + (size_t)(row0 + 8) * FF + col) = hi;
        }
    }

    // ---- fused column-sum (Htot) for the 12 H matrices ----
    if (r < 12) {
        const int inst = b * 12 + r;
        #pragma unroll
        for (int j = 0; j < 4; j++) {
            float s0 = 0.f, s1 = 0.f;
            #pragma unroll
            for (int i = 0; i < 2; i++) {
                s0 += acc[i][j].x + acc[i][j].z;
                s1 += acc[i][j].y + acc[i][j].w;
            }
            #pragma unroll
            for (int off = 16; off >= 4; off >>= 1) {
                s0 += __shfl_down_sync(0xffffffffu, s0, off);
                s1 += __shfl_down_sync(0xffffffffu, s1, off);
            }
            if (lane < 4) {
                const int col = (wn * 4 + j) * 8 + 2 * lane;
                atomicAdd(&g_Htot[inst * FF + col],     s0 + 32.f * bv[col]);
                atomicAdd(&g_Htot[inst * FF + col + 1], s1 + 32.f * bv[col + 1]);
            }
        }
    }
}

// ==================== attention e-vectors (esrc incl. bias) =====================
__global__ __launch_bounds__(256) void evec_kernel(
    const float* __restrict__ att_w,  const float* __restrict__ att_b,
    const float* __restrict__ fwd_aw, const float* __restrict__ fwd_ab,
    const float* __restrict__ bwd_aw, const float* __restrict__ bwd_ab)
{
    const int op = blockIdx.y, b = blockIdx.z;
    const int warp = threadIdx.x >> 5, lane = threadIdx.x & 31;
    const int row = blockIdx.x * 8 + warp;
    const int hsel = (op < 6) ? op : 5;
    const float* hrow = g_H + (((size_t)b * 12 + hsel) * NN + row) * FF;
    const float* w; float ab;
    if (op < 6)      { w = att_w  + op * 2 * FF;       ab = att_b[op]; }
    else if (op < 9) { w = fwd_aw + (op - 6) * 2 * FF; ab = fwd_ab[op - 6]; }
    else             { w = bwd_aw + (op - 9) * 2 * FF; ab = bwd_ab[op - 9]; }
    float s1 = 0.f, s2 = 0.f;
    #pragma unroll
    for (int q = 0; q < 4; q++) {
        float hv = hrow[lane + 32 * q];
        s1 += hv * w[lane + 32 * q];
        s2 += hv * w[FF + lane + 32 * q];
    }
    #pragma unroll
    for (int off = 16; off > 0; off >>= 1) {
        s1 += __shfl_down_sync(0xffffffffu, s1, off);
        s2 += __shfl_down_sync(0xffffffffu, s2, off);
    }
    if (lane == 0) {
        g_esrc[(b * 12 + op) * NN + row] = s1 + ab;
        g_edst[(b * 12 + op) * NN + row] = s2;
    }
}

// ======================= fused masked attention + aggregation ===================
// out_row = scale*(Htot + sum_e (exp(lrelu(e))-1)*h_j) / (1024 + sum_e(exp-1))
// h in smem as fp32; lane owns 4 contiguous features -> LDS.128 + 2x fma.rn.f32x2.
#define CHUNK 128
#define AGG_SMEM (CHUNK * FF * 4 + CHUNK * 4)

__device__ __forceinline__ void ffma2(unsigned long long& acc,
                                      unsigned long long a, unsigned long long b)
{
    asm("fma.rn.f32x2 %0, %1, %2, %0;" : "+l"(acc) : "l"(a), "l"(b));
}

__global__ __launch_bounds__(512) void agg_kernel()
{
    extern __shared__ __align__(16) char smraw[];
    float* hs     = (float*)smraw;                              // [CHUNK][FF] fp32
    float* edst_s = (float*)(smraw + CHUNK * FF * 4);           // [CHUNK]

    const int op = blockIdx.y, b = blockIdx.z;
    const int inst = b * 12 + op;
    const float* Hm = g_H + (size_t)inst * NN * FF;

    const uint32_t* rowbits = nullptr;
    const uint32_t* dwords = nullptr;
    float scale = 1.0f;
    if (op < 3)      rowbits = g_rowbits + (((size_t)(b * 6 + op)) * NN) * 32;
    else if (op < 6) dwords = g_dbits + (b * 3 + (op - 3)) * 32;
    else if (op < 9) { rowbits = g_rowbits + (((size_t)(b * 6 + op - 3)) * NN) * 32; scale = 0.5f; }
    else             { rowbits = g_bitsT + (((size_t)(b * 3 + op - 9)) * NN) * 32;   scale = 0.5f; }

    const int warp = threadIdx.x >> 5, lane = threadIdx.x & 31;
    const int row0 = blockIdx.x * 256 + warp * 16;
    const float* esrc_g = g_esrc + inst * NN;
    const float* edst_g = g_edst + inst * NN;

    unsigned long long U01[16], U23[16];
    float Wsum[16];
    #pragma unroll
    for (int i = 0; i < 16; i++) { U01[i] = 0ull; U23[i] = 0ull; Wsum[i] = 0.f; }

    for (int c = 0; c < NN / CHUNK; c++) {
        const int cb = c * CHUNK;
        for (int t = threadIdx.x; t < CHUNK * 32; t += 512) {
            int jr = t >> 5, q = t & 31;
            *(float4*)(hs + jr * FF + q * 4) =
                *(const float4*)(Hm + (size_t)(cb + jr) * FF + q * 4);
        }
        if (threadIdx.x < CHUNK) edst_s[threadIdx.x] = edst_g[cb + threadIdx.x];
        __syncthreads();

        #pragma unroll
        for (int i = 0; i < 16; i++) {
            const int row = row0 + i;
            bool active = true;
            if (dwords) active = ((__ldg(dwords + (row >> 5)) >> (row & 31)) & 1u) != 0;
            if (active) {
                const uint32_t* mrow = dwords ? (dwords + (cb >> 5))
                                              : (rowbits + (size_t)row * 32 + (cb >> 5));
                uint32_t mw = (lane < 4) ? __ldg(mrow + lane) : 0u;
                const float esri = __ldg(esrc_g + row);
                #pragma unroll
                for (int wi = 0; wi < 4; wi++) {
                    unsigned m = __shfl_sync(0xffffffffu, mw, wi);
                    while (m) {
                        int bpos = __ffs(m) - 1; m &= m - 1;
                        int jl = wi * 32 + bpos;
                        float l = esri + edst_s[jl];
                        l = l > 0.f ? l : 0.01f * l;
                        float u = __expf(l) - 1.0f;
                        Wsum[i] += u;
                        unsigned long long uu;
                        asm("mov.b64 %0, {%1, %1};" : "=l"(uu) : "r"(__float_as_uint(u)));
                        ulonglong2 hv = *(const ulonglong2*)(hs + jl * FF + 4 * lane);
                        ffma2(U01[i], uu, hv.x);
                        ffma2(U23[i], uu, hv.y);
                    }
                }
            }
        }
        __syncthreads();
    }

    // epilogue: out cols 4*lane .. 4*lane+3
    const float4 ht4 = *(const float4*)(g_Htot + inst * FF + 4 * lane);
    float* part = g_part[op] + ((size_t)b * NN + row0) * FF;
    #pragma unroll
    for (int i = 0; i < 16; i++) {
        float inv = scale / (1024.0f + Wsum[i]);
        float u0 = __uint_as_float((unsigned)(U01[i] & 0xffffffffull));
        float u1 = __uint_as_float((unsigned)(U01[i] >> 32));
        float u2 = __uint_as_float((unsigned)(U23[i] & 0xffffffffull));
        float u3 = __uint_as_float((unsigned)(U23[i] >> 32));
        float4 o;
        o.x = (ht4.x + u0) * inv; o.y = (ht4.y + u1) * inv;
        o.z = (ht4.z + u2) * inv; o.w = (ht4.w + u3) * inv;
        *(float4*)(part + (size_t)i * FF + 4 * lane) = o;
    }
}

// =========================== final reduce + ReLU ================================
__global__ __launch_bounds__(256) void reduce_kernel(float* __restrict__ out)
{
    const int i = blockIdx.x * blockDim.x + threadIdx.x;   // float4 index
    float4 v = ((const float4*)g_outacc)[i];
    #pragma unroll
    for (int op = 0; op < 12; op++) {
        float4 p = ((const float4*)(g_part[op]))[i];
        v.x += p.x; v.y += p.y; v.z += p.z; v.w += p.w;
    }
    v.x = fmaxf(v.x, 0.f); v.y = fmaxf(v.y, 0.f);
    v.z = fmaxf(v.z, 0.f); v.w = fmaxf(v.w, 0.f);
    ((float4*)out)[i] = v;
}

// ================================================================================
extern "C" void kernel_launch(void* const* d_in, const int* in_sizes, int n_in,
                              void* d_out, int out_size)
{
    const float* batch_x    = (const float*)d_in[0];
    const float* batch_adjs = (const float*)d_in[1];
    const float* fc_w       = (const float*)d_in[2];
    const float* fc_b       = (const float*)d_in[3];
    const float* att_w      = (const float*)d_in[4];
    const float* att_b      = (const float*)d_in[5];
    const float* fwd_fc_w   = (const float*)d_in[6];
    const float* fwd_fc_b   = (const float*)d_in[7];
    const float* fwd_att_w  = (const float*)d_in[8];
    const float* fwd_att_b  = (const float*)d_in[9];
    const float* bwd_fc_w   = (const float*)d_in[10];
    const float* bwd_fc_b   = (const float*)d_in[11];
    const float* bwd_att_w  = (const float*)d_in[12];
    const float* bwd_att_b  = (const float*)d_in[13];
    const float* self_w     = (const float*)d_in[14];
    const float* self_b     = (const float*)d_in[15];
    const float* bias       = (const float*)d_in[16];
    float* out = (float*)d_out;

    static bool attr_done = false;
    if (!attr_done) {
        cudaFuncSetAttribute(agg_kernel, cudaFuncAttributeMaxDynamicSharedMemorySize, AGG_SMEM);
        cudaFuncSetAttribute(gemm_kernel, cudaFuncAttributeMaxDynamicSharedMemorySize, GEMM_SMEM);
        attr_done = true;
    }

    bitpack_kernel<<<dim3(32, 7, 8), 256>>>(batch_adjs);                  // launch 0 (zeroes Htot too)
    gemm_kernel<<<dim3(8, 13, 8), 512, GEMM_SMEM>>>(batch_x, fc_w, fc_b, // launch 1
                                                    fwd_fc_w, fwd_fc_b,
                                                    bwd_fc_w, bwd_fc_b,
                                                    self_w, self_b, bias);
    evec_kernel<<<dim3(128, 12, 8), 256>>>(att_w, att_b, fwd_att_w,       // launch 2
                                           fwd_att_b, bwd_att_w, bwd_att_b);
    agg_kernel<<<dim3(4, 12, 8), 512, AGG_SMEM>>>();                      // launch 3 (ncu target)
    reduce_kernel<<<1024, 256>>>(out);                                    // launch 4
}